// round 10
// baseline (speedup 1.0000x reference)
#include <cuda_runtime.h>
#include <cuda_fp16.h>
#include <cstdint>

#define BATCH   2048
#define IN_DIM  512
#define OUT_DIM 512
#define SDIM    8
#define KDIM    4096
#define ROWLEN  513

#define BM 128
#define BN 64
#define CHUNK 64
#define NTH 512                      // 2 s-groups x 8 warps
#define GITER 32                     // 8 chunks x 4 s per group

#define SROWB 144
#define A_BUF_BYTES (BM * SROWB)     // 18432, x2 (shared by both groups)
#define B_BUF_BYTES (BN * SROWB)     // 9216, x3 per group
#define OFF_A 0
#define OFF_B (2 * A_BUF_BYTES)                    // 36864
#define OFF_BASIS (OFF_B + 6 * B_BUF_BYTES)        // 92160
#define OFF_BW (OFF_BASIS + BM * SDIM * 4)         // 96256
#define SMEM_TOTAL (OFF_BW + SDIM * BN * 4)        // 98304
#define RED_STRIDE 66

// ---------------------------------------------------------------------------
__device__ __forceinline__ uint32_t smem_u32(const void* p) {
    uint32_t a;
    asm("{ .reg .u64 t; cvta.to.shared.u64 t, %1; cvt.u32.u64 %0, t; }"
        : "=r"(a) : "l"(p));
    return a;
}
__device__ __forceinline__ void cp16(uint32_t dst, const void* src) {
    asm volatile("cp.async.cg.shared.global [%0], [%1], 16;"
                 :: "r"(dst), "l"(src) : "memory");
}
#define CP_COMMIT() asm volatile("cp.async.commit_group;" ::: "memory")
#define CP_WAIT(n)  asm volatile("cp.async.wait_group %0;" :: "n"(n) : "memory")

__device__ __forceinline__ void ldm_x4(uint32_t* r, uint32_t addr) {
    asm volatile("ldmatrix.sync.aligned.m8n8.x4.shared.b16 {%0,%1,%2,%3}, [%4];"
                 : "=r"(r[0]), "=r"(r[1]), "=r"(r[2]), "=r"(r[3]) : "r"(addr));
}
__device__ __forceinline__ void mma_f16(float* d, const uint32_t* a, const uint32_t* b) {
    asm volatile(
        "mma.sync.aligned.m16n8k16.row.col.f32.f16.f16.f32 "
        "{%0,%1,%2,%3}, {%4,%5,%6,%7}, {%8,%9}, {%0,%1,%2,%3};"
        : "+f"(d[0]), "+f"(d[1]), "+f"(d[2]), "+f"(d[3])
        : "r"(a[0]), "r"(a[1]), "r"(a[2]), "r"(a[3]), "r"(b[0]), "r"(b[1]));
}

// ---------------------------------------------------------------------------
__device__ float g_basis[BATCH * SDIM];
__device__ __align__(16) __half g_F[BATCH * IN_DIM];
__device__ __align__(16) __half g_Wt[OUT_DIM * KDIM];   // Wt[o][s*512+i]

// ---------------------------------------------------------------------------
// Merged prep: blocks 0..255 -> F fp16 + basis; blocks 256..1279 -> W transpose
// ---------------------------------------------------------------------------
__global__ void prep_kernel(const float* __restrict__ inputs,
                            const float* __restrict__ W) {
    __shared__ float t[64][33];
    const int bid = blockIdx.x;
    const int tid = threadIdx.x;
    if (bid < 256) {
        const int t0 = bid * 256 + tid;
#pragma unroll
        for (int j = 0; j < 8; ++j) {
            int g = t0 + j * 65536;
            int b = g >> 8, p = g & 255;
            const float* row = inputs + (size_t)b * ROWLEN;
            float x0 = __ldg(row + 1 + 2 * p);
            float x1 = __ldg(row + 2 + 2 * p);
            __half2 h = __floats2half2_rn(x0, x1);
            ((uint32_t*)g_F)[g] = *(uint32_t*)&h;
        }
        if (t0 < BATCH) {
            float tt = __ldg(&inputs[(size_t)t0 * ROWLEN]);
            float t2 = tt * tt, t3 = t2 * tt;
            float* dst = &g_basis[t0 * SDIM];
            dst[0] = 1.0f; dst[1] = tt; dst[2] = t2; dst[3] = t3;
            const float kn[4] = {0.2f, 0.4f, 0.6f, 0.8f};
#pragma unroll
            for (int j = 0; j < 4; ++j) {
                float u = fmaxf(tt - kn[j], 0.0f);
                dst[4 + j] = u * u * u;
            }
        }
    } else {
        const int wb = bid - 256;
        const int s  = wb >> 7;
        const int i0 = (wb & 7) * 64;
        const int o0 = ((wb >> 3) & 15) * 32;
        const int tx = tid & 31, ty = tid >> 5;
        for (int r = ty; r < 64; r += 8)
            t[r][tx] = W[((size_t)s << 18) + (size_t)(i0 + r) * 512 + o0 + tx];
        __syncthreads();
        for (int r = ty; r < 32; r += 8) {
            __half2 h = __floats2half2_rn(t[2 * tx][r], t[2 * tx + 1][r]);
            *(uint32_t*)&g_Wt[(size_t)(o0 + r) * KDIM + s * 512 + i0 + 2 * tx] =
                *(uint32_t*)&h;
        }
    }
}

// ---------------------------------------------------------------------------
// GEMM: 2 s-split groups x 8 warps, warp tile 32x32 (4 warps/SMSP).
// Shared A tile (one load per chunk), B per group. Basis folded in registers.
// ---------------------------------------------------------------------------
__global__ __launch_bounds__(NTH, 1)
void vclinear_mma_kernel(const float* __restrict__ bwts, float* __restrict__ out) {
    extern __shared__ char smem[];
    const uint32_t sb = smem_u32(smem);
    const int tid  = threadIdx.x;
    const int g    = tid >> 8;              // s-group 0/1
    const int ltid = tid & 255;
    const int gwid = (tid >> 5) & 7;        // warp within group
    const int lane = tid & 31;
    const int block_n = blockIdx.x * BN;
    const int block_m = blockIdx.y * BM;

    float* sBasis = (float*)(smem + OFF_BASIS);
    float* sBw    = (float*)(smem + OFF_BW);
    for (int q = tid; q < BM * SDIM; q += NTH)
        sBasis[q] = g_basis[(block_m + (q >> 3)) * SDIM + (q & 7)];
    for (int q = tid; q < SDIM * BN; q += NTH)
        sBw[q] = bwts[(q >> 6) * OUT_DIM + block_n + (q & 63)];
    __syncthreads();

    // A load: all 512 threads, 2 cp16 each (128 rows x 8 chunks)
    const int ca  = tid & 7;
    const int ra  = tid >> 3;               // 0..63
    // B load: per group, 256 threads, 2 cp16 each (64 rows x 8 chunks)
    const int cb  = ltid & 7;
    const int rb  = ltid >> 3;              // 0..31

#define LOAD_A(chunk) do {                                                       \
    const uint32_t d = sb + OFF_A + ((chunk) & 1) * A_BUF_BYTES;                 \
    const size_t base = (size_t)block_m * IN_DIM + (chunk) * CHUNK + ca * 8;     \
    cp16(d + ra * SROWB + ca * 16,        g_F + base + (size_t)ra * IN_DIM);     \
    cp16(d + (ra + 64) * SROWB + ca * 16, g_F + base + (size_t)(ra + 64) * IN_DIM);\
} while (0)

#define LOAD_B(it, buf) do {                                                     \
    const uint32_t d = sb + OFF_B + (g * 3 + (buf)) * B_BUF_BYTES;               \
    const size_t base = (size_t)block_n * KDIM + (g * 4 + ((it) & 3)) * 512      \
                      + ((it) >> 2) * CHUNK + cb * 8;                            \
    cp16(d + rb * SROWB + cb * 16,        g_Wt + base + (size_t)rb * KDIM);      \
    cp16(d + (rb + 32) * SROWB + cb * 16, g_Wt + base + (size_t)(rb + 32) * KDIM);\
} while (0)

    // warp tiling within group: 4m x 2n, warp tile 32x32
    const int m0 = (gwid & 3) * 32;
    const int n0 = (gwid >> 2) * 32;
    const uint32_t aoff = (m0 + (lane & 15)) * SROWB + (lane >> 4) * 16;
    const uint32_t boff = (n0 + (lane & 7) + ((lane >> 4) << 3)) * SROWB
                        + ((lane >> 3) & 1) * 16;

    float acc[2][4][4];     // basis-folded output (warp tile 32x32)
    float accs[2][4][4];    // per-(chunk,s) partial
#pragma unroll
    for (int i = 0; i < 2; ++i)
#pragma unroll
        for (int j = 0; j < 4; ++j)
#pragma unroll
            for (int r = 0; r < 4; ++r) { acc[i][j][r] = 0.0f; accs[i][j][r] = 0.0f; }

    // prologue: distance-2 pipeline, 3 B buffers
    LOAD_A(0);
    LOAD_B(0, 0);
    CP_COMMIT();
    LOAD_B(1, 1);
    CP_COMMIT();

    for (int it = 0; it < GITER; ++it) {
        CP_WAIT(1);
        __syncthreads();

        const int nxt = it + 2;
        if (nxt < GITER) {
            if ((nxt & 3) == 0) LOAD_A(nxt >> 2);   // A(chunk+1) two iters early
            LOAD_B(nxt, nxt % 3);
        }
        CP_COMMIT();

        const uint32_t aB = sb + OFF_A + ((it >> 2) & 1) * A_BUF_BYTES;
        const uint32_t bB = sb + OFF_B + (g * 3 + it % 3) * B_BUF_BYTES;
#pragma unroll
        for (int kk = 0; kk < 4; ++kk) {
            uint32_t a[2][4], b[2][4];
            ldm_x4(a[0], aB + aoff + kk * 32);
            ldm_x4(a[1], aB + aoff + 16 * SROWB + kk * 32);
            ldm_x4(b[0], bB + boff + kk * 32);
            ldm_x4(b[1], bB + boff + 16 * SROWB + kk * 32);
#pragma unroll
            for (int ma = 0; ma < 2; ++ma)
#pragma unroll
                for (int na = 0; na < 4; ++na)
                    mma_f16(accs[ma][na], a[ma], &b[na >> 1][(na & 1) * 2]);
        }

        // fold accs into acc with basis[row][s]
        const int s = g * 4 + (it & 3);
#pragma unroll
        for (int ma = 0; ma < 2; ++ma) {
#pragma unroll
            for (int half = 0; half < 2; ++half) {
                const int row = m0 + ma * 16 + (lane >> 2) + half * 8;
                const float bsv = sBasis[row * SDIM + s];
#pragma unroll
                for (int na = 0; na < 4; ++na) {
#pragma unroll
                    for (int j = 0; j < 2; ++j) {
                        acc[ma][na][half * 2 + j] =
                            fmaf(bsv, accs[ma][na][half * 2 + j],
                                 acc[ma][na][half * 2 + j]);
                        accs[ma][na][half * 2 + j] = 0.0f;
                    }
                }
            }
        }
    }

    // cross-group reduction: g1 stages partials, g0 adds + bias + store
    float* red = (float*)(smem + OFF_A);   // 33792 B in dead A/B space
    __syncthreads();
    if (g == 1) {
#pragma unroll
        for (int ma = 0; ma < 2; ++ma)
#pragma unroll
            for (int half = 0; half < 2; ++half) {
                const int row = m0 + ma * 16 + (lane >> 2) + half * 8;
#pragma unroll
                for (int na = 0; na < 4; ++na) {
                    const int col = n0 + na * 8 + 2 * (lane & 3);
                    *(float2*)&red[row * RED_STRIDE + col] =
                        make_float2(acc[ma][na][half * 2], acc[ma][na][half * 2 + 1]);
                }
            }
    }
    __syncthreads();
    if (g == 0) {
#pragma unroll
        for (int ma = 0; ma < 2; ++ma) {
#pragma unroll
            for (int half = 0; half < 2; ++half) {
                const int row = m0 + ma * 16 + (lane >> 2) + half * 8;
                float bsv[SDIM];
#pragma unroll
                for (int s = 0; s < SDIM; ++s) bsv[s] = sBasis[row * SDIM + s];
#pragma unroll
                for (int na = 0; na < 4; ++na) {
                    const int col = n0 + na * 8 + 2 * (lane & 3);
                    float b0r = 0.0f, b1r = 0.0f;
#pragma unroll
                    for (int s = 0; s < SDIM; ++s) {
                        b0r = fmaf(bsv[s], sBw[s * BN + col], b0r);
                        b1r = fmaf(bsv[s], sBw[s * BN + col + 1], b1r);
                    }
                    float2 o = *(float2*)&red[row * RED_STRIDE + col];
                    float2 v;
                    v.x = acc[ma][na][half * 2 + 0] + o.x + b0r;
                    v.y = acc[ma][na][half * 2 + 1] + o.y + b1r;
                    *(float2*)&out[(size_t)(block_m + row) * OUT_DIM + block_n + col] = v;
                }
            }
        }
    }
}

// ---------------------------------------------------------------------------
extern "C" void kernel_launch(void* const* d_in, const int* in_sizes, int n_in,
                              void* d_out, int out_size) {
    const float* inputs = (const float*)d_in[0];
    const float* W      = (const float*)d_in[1];
    const float* bwts   = (const float*)d_in[2];
    float* out          = (float*)d_out;

    cudaFuncSetAttribute(vclinear_mma_kernel,
                         cudaFuncAttributeMaxDynamicSharedMemorySize, SMEM_TOTAL);

    prep_kernel<<<1280, 256>>>(inputs, W);

    dim3 grid(OUT_DIM / BN, BATCH / BM);   // 128 CTAs
    vclinear_mma_kernel<<<grid, NTH, SMEM_TOTAL>>>(bwts, out);
}

// round 11
// speedup vs baseline: 1.0556x; 1.0556x over previous
#include <cuda_runtime.h>
#include <cuda_fp16.h>
#include <cstdint>

#define BATCH   2048
#define IN_DIM  512
#define OUT_DIM 512
#define SDIM    8
#define KDIM    4096
#define ROWLEN  513

#define BM 128
#define BN 32
#define CHUNK 64
#define NTH 256                      // 2 s-groups x 4 warps
#define GITER 32                     // 8 chunks x 4 s per group

#define SROWB 144
#define A_BUF_BYTES (BM * SROWB)     // 18432, x2 (shared by both groups)
#define B_BUF_BYTES (BN * SROWB)     // 4608, x3 per group
#define OFF_A 0
#define OFF_B (2 * A_BUF_BYTES)                    // 36864
#define OFF_BASIS (OFF_B + 6 * B_BUF_BYTES)        // 64512
#define OFF_BW (OFF_BASIS + BM * SDIM * 4)         // 68608
#define SMEM_TOTAL (OFF_BW + SDIM * BN * 4)        // 69632
#define RED_STRIDE 34

// ---------------------------------------------------------------------------
__device__ __forceinline__ uint32_t smem_u32(const void* p) {
    uint32_t a;
    asm("{ .reg .u64 t; cvta.to.shared.u64 t, %1; cvt.u32.u64 %0, t; }"
        : "=r"(a) : "l"(p));
    return a;
}
__device__ __forceinline__ void cp16(uint32_t dst, const void* src) {
    asm volatile("cp.async.cg.shared.global [%0], [%1], 16;"
                 :: "r"(dst), "l"(src) : "memory");
}
#define CP_COMMIT() asm volatile("cp.async.commit_group;" ::: "memory")
#define CP_WAIT(n)  asm volatile("cp.async.wait_group %0;" :: "n"(n) : "memory")

__device__ __forceinline__ void ldm_x4(uint32_t* r, uint32_t addr) {
    asm volatile("ldmatrix.sync.aligned.m8n8.x4.shared.b16 {%0,%1,%2,%3}, [%4];"
                 : "=r"(r[0]), "=r"(r[1]), "=r"(r[2]), "=r"(r[3]) : "r"(addr));
}
__device__ __forceinline__ void mma_f16(float* d, const uint32_t* a, const uint32_t* b) {
    asm volatile(
        "mma.sync.aligned.m16n8k16.row.col.f32.f16.f16.f32 "
        "{%0,%1,%2,%3}, {%4,%5,%6,%7}, {%8,%9}, {%0,%1,%2,%3};"
        : "+f"(d[0]), "+f"(d[1]), "+f"(d[2]), "+f"(d[3])
        : "r"(a[0]), "r"(a[1]), "r"(a[2]), "r"(a[3]), "r"(b[0]), "r"(b[1]));
}
__device__ __forceinline__ uint32_t hmul2u(uint32_t a, uint32_t b) {
    __half2 r = __hmul2(*(__half2*)&a, *(__half2*)&b);
    return *(uint32_t*)&r;
}

// ---------------------------------------------------------------------------
__device__ float g_basis[BATCH * SDIM];
__device__ __align__(16) __half g_F[BATCH * IN_DIM];
__device__ __align__(16) __half g_Wt[OUT_DIM * KDIM];   // Wt[o][s*512+i]

// ---------------------------------------------------------------------------
// Merged prep: blocks 0..255 -> F fp16 + basis; blocks 256..1279 -> W transpose
// ---------------------------------------------------------------------------
__global__ void prep_kernel(const float* __restrict__ inputs,
                            const float* __restrict__ W) {
    __shared__ float t[64][33];
    const int bid = blockIdx.x;
    const int tid = threadIdx.x;
    if (bid < 256) {
        const int t0 = bid * 256 + tid;
#pragma unroll
        for (int j = 0; j < 8; ++j) {
            int g = t0 + j * 65536;
            int b = g >> 8, p = g & 255;
            const float* row = inputs + (size_t)b * ROWLEN;
            float x0 = __ldg(row + 1 + 2 * p);
            float x1 = __ldg(row + 2 + 2 * p);
            __half2 h = __floats2half2_rn(x0, x1);
            ((uint32_t*)g_F)[g] = *(uint32_t*)&h;
        }
        if (t0 < BATCH) {
            float tt = __ldg(&inputs[(size_t)t0 * ROWLEN]);
            float t2 = tt * tt, t3 = t2 * tt;
            float* dst = &g_basis[t0 * SDIM];
            dst[0] = 1.0f; dst[1] = tt; dst[2] = t2; dst[3] = t3;
            const float kn[4] = {0.2f, 0.4f, 0.6f, 0.8f};
#pragma unroll
            for (int j = 0; j < 4; ++j) {
                float u = fmaxf(tt - kn[j], 0.0f);
                dst[4 + j] = u * u * u;
            }
        }
    } else {
        const int wb = bid - 256;
        const int s  = wb >> 7;
        const int i0 = (wb & 7) * 64;
        const int o0 = ((wb >> 3) & 15) * 32;
        const int tx = tid & 31, ty = tid >> 5;
        for (int r = ty; r < 64; r += 8)
            t[r][tx] = W[((size_t)s << 18) + (size_t)(i0 + r) * 512 + o0 + tx];
        __syncthreads();
        for (int r = ty; r < 32; r += 8) {
            __half2 h = __floats2half2_rn(t[2 * tx][r], t[2 * tx + 1][r]);
            *(uint32_t*)&g_Wt[(size_t)(o0 + r) * KDIM + s * 512 + i0 + 2 * tx] =
                *(uint32_t*)&h;
        }
    }
}

// ---------------------------------------------------------------------------
// GEMM: 2 s-groups x 4 warps, warp tile 32x32; A fragments register-resident
// per chunk, scaled by fp16 basis per s (fold-free); 2 CTAs/SM.
// ---------------------------------------------------------------------------
__global__ __launch_bounds__(NTH, 2)
void vclinear_mma_kernel(const float* __restrict__ bwts, float* __restrict__ out) {
    extern __shared__ char smem[];
    const uint32_t sb = smem_u32(smem);
    const int tid  = threadIdx.x;
    const int g    = tid >> 7;              // s-group 0/1
    const int ltid = tid & 127;
    const int gwid = (tid >> 5) & 3;        // warp within group
    const int lane = tid & 31;
    const int block_n = blockIdx.x * BN;
    const int block_m = blockIdx.y * BM;

    float* sBasis = (float*)(smem + OFF_BASIS);
    float* sBw    = (float*)(smem + OFF_BW);
    for (int q = tid; q < BM * SDIM; q += NTH)
        sBasis[q] = g_basis[(block_m + (q >> 3)) * SDIM + (q & 7)];
    for (int q = tid; q < SDIM * BN; q += NTH)
        sBw[q] = bwts[(q >> 5) * OUT_DIM + block_n + (q & 31)];
    __syncthreads();

    // A load: all 256 threads, 4 cp16 each (128 rows x 8 chunks of 16B)
    const int ca  = tid & 7;
    const int ra  = tid >> 3;               // 0..31
    // B load: per group, 128 threads, 2 cp16 each (32 rows x 8)
    const int cb  = ltid & 7;
    const int rb  = ltid >> 3;              // 0..15

#define LOAD_A(chunk) do {                                                       \
    const uint32_t d = sb + OFF_A + ((chunk) & 1) * A_BUF_BYTES;                 \
    const size_t base = (size_t)block_m * IN_DIM + (chunk) * CHUNK + ca * 8;     \
    _Pragma("unroll")                                                            \
    for (int j = 0; j < 4; ++j) {                                                \
        int row = ra + j * 32;                                                   \
        cp16(d + row * SROWB + ca * 16, g_F + base + (size_t)row * IN_DIM);      \
    }                                                                            \
} while (0)

#define LOAD_B(it, buf) do {                                                     \
    const uint32_t d = sb + OFF_B + (g * 3 + (buf)) * B_BUF_BYTES;               \
    const size_t base = (size_t)block_n * KDIM + (g * 4 + ((it) & 3)) * 512      \
                      + ((it) >> 2) * CHUNK + cb * 8;                            \
    cp16(d + rb * SROWB + cb * 16,        g_Wt + base + (size_t)rb * KDIM);      \
    cp16(d + (rb + 16) * SROWB + cb * 16, g_Wt + base + (size_t)(rb + 16) * KDIM);\
} while (0)

    // warp tiling within group: 4m x 1n, warp tile 32x32
    const int m0 = gwid * 32;
    const uint32_t aoff = (m0 + (lane & 15)) * SROWB + (lane >> 4) * 16;
    const uint32_t boff = ((lane & 7) + ((lane >> 4) << 3)) * SROWB
                        + ((lane >> 3) & 1) * 16;

    uint32_t af[4][2][4];   // A fragments, register-resident per chunk [kk][ma]
    float acc[2][4][4];
#pragma unroll
    for (int i = 0; i < 2; ++i)
#pragma unroll
        for (int j = 0; j < 4; ++j)
#pragma unroll
            for (int r = 0; r < 4; ++r) acc[i][j][r] = 0.0f;

    // prologue: distance-2, 3 B buffers
    LOAD_A(0);
    LOAD_B(0, 0);
    CP_COMMIT();
    LOAD_B(1, 1);
    CP_COMMIT();

    for (int it = 0; it < GITER; ++it) {
        CP_WAIT(1);
        __syncthreads();

        const int nxt = it + 2;
        if (nxt < GITER) {
            if ((nxt & 3) == 0) LOAD_A(nxt >> 2);
            LOAD_B(nxt, nxt % 3);
        }
        CP_COMMIT();

        // chunk start: pull A tile into registers (reused for 4 s-iters)
        if ((it & 3) == 0) {
            const uint32_t aB = sb + OFF_A + ((it >> 2) & 1) * A_BUF_BYTES;
#pragma unroll
            for (int kk = 0; kk < 4; ++kk)
#pragma unroll
                for (int ma = 0; ma < 2; ++ma)
                    ldm_x4(af[kk][ma], aB + aoff + ma * 16 * SROWB + kk * 32);
        }

        // per-s basis scalars as half2 (rows r, r+8, r+16, r+24)
        const int s = g * 4 + (it & 3);
        uint32_t hb[4];
#pragma unroll
        for (int i = 0; i < 4; ++i) {
            float bv = sBasis[(m0 + (lane >> 2) + 8 * i) * SDIM + s];
            __half2 h = __float2half2_rn(bv);
            hb[i] = *(uint32_t*)&h;
        }

        const uint32_t bB = sb + OFF_B + (g * 3 + it % 3) * B_BUF_BYTES;
#pragma unroll
        for (int kk = 0; kk < 4; ++kk) {
            uint32_t bt[2][4];
            ldm_x4(bt[0], bB + boff + kk * 32);
            ldm_x4(bt[1], bB + boff + 16 * SROWB + kk * 32);
#pragma unroll
            for (int ma = 0; ma < 2; ++ma) {
                uint32_t at[4];
                at[0] = hmul2u(af[kk][ma][0], hb[2 * ma]);
                at[1] = hmul2u(af[kk][ma][1], hb[2 * ma + 1]);
                at[2] = hmul2u(af[kk][ma][2], hb[2 * ma]);
                at[3] = hmul2u(af[kk][ma][3], hb[2 * ma + 1]);
#pragma unroll
                for (int na = 0; na < 4; ++na)
                    mma_f16(acc[ma][na], at, &bt[na >> 1][(na & 1) * 2]);
            }
        }
    }

    // cross-group reduction: g1 stages partials, g0 adds + bias + store
    float* red = (float*)(smem + OFF_A);
    __syncthreads();
    if (g == 1) {
#pragma unroll
        for (int ma = 0; ma < 2; ++ma)
#pragma unroll
            for (int half = 0; half < 2; ++half) {
                const int row = m0 + ma * 16 + (lane >> 2) + half * 8;
#pragma unroll
                for (int na = 0; na < 4; ++na) {
                    const int col = na * 8 + 2 * (lane & 3);
                    *(float2*)&red[row * RED_STRIDE + col] =
                        make_float2(acc[ma][na][half * 2], acc[ma][na][half * 2 + 1]);
                }
            }
    }
    __syncthreads();
    if (g == 0) {
#pragma unroll
        for (int ma = 0; ma < 2; ++ma) {
#pragma unroll
            for (int half = 0; half < 2; ++half) {
                const int row = m0 + ma * 16 + (lane >> 2) + half * 8;
                float bsv[SDIM];
#pragma unroll
                for (int s = 0; s < SDIM; ++s) bsv[s] = sBasis[row * SDIM + s];
#pragma unroll
                for (int na = 0; na < 4; ++na) {
                    const int col = na * 8 + 2 * (lane & 3);
                    float b0r = 0.0f, b1r = 0.0f;
#pragma unroll
                    for (int s = 0; s < SDIM; ++s) {
                        b0r = fmaf(bsv[s], sBw[s * BN + col], b0r);
                        b1r = fmaf(bsv[s], sBw[s * BN + col + 1], b1r);
                    }
                    float2 o = *(float2*)&red[row * RED_STRIDE + col];
                    float2 v;
                    v.x = acc[ma][na][half * 2 + 0] + o.x + b0r;
                    v.y = acc[ma][na][half * 2 + 1] + o.y + b1r;
                    *(float2*)&out[(size_t)(block_m + row) * OUT_DIM + block_n + col] = v;
                }
            }
        }
    }
}

// ---------------------------------------------------------------------------
extern "C" void kernel_launch(void* const* d_in, const int* in_sizes, int n_in,
                              void* d_out, int out_size) {
    const float* inputs = (const float*)d_in[0];
    const float* W      = (const float*)d_in[1];
    const float* bwts   = (const float*)d_in[2];
    float* out          = (float*)d_out;

    cudaFuncSetAttribute(vclinear_mma_kernel,
                         cudaFuncAttributeMaxDynamicSharedMemorySize, SMEM_TOTAL);

    prep_kernel<<<1280, 256>>>(inputs, W);

    dim3 grid(OUT_DIM / BN, BATCH / BM);   // (16, 16) = 256 CTAs, 2/SM
    vclinear_mma_kernel<<<grid, NTH, SMEM_TOTAL>>>(bwts, out);
}

// round 12
// speedup vs baseline: 1.1722x; 1.1105x over previous
#include <cuda_runtime.h>
#include <cuda_fp16.h>
#include <cstdint>

#define BATCH   2048
#define IN_DIM  512
#define OUT_DIM 512
#define SDIM    8
#define KDIM    4096
#define ROWLEN  513

#define BM 128
#define BN 32
#define CHUNK 64
#define NTH 256                      // 2 s-groups x 4 warps

#define SROWB 144
#define A_BUF_BYTES (BM * SROWB)     // 18432 x2
#define OFF_A 0
#define OFF_BASIS (2 * A_BUF_BYTES)                // 36864
#define OFF_BW (OFF_BASIS + BM * SDIM * 4)         // 40960
#define SMEM_TOTAL (OFF_BW + SDIM * BN * 4)        // 41984
#define RED_STRIDE 34

// ---------------------------------------------------------------------------
__device__ __forceinline__ uint32_t smem_u32(const void* p) {
    uint32_t a;
    asm("{ .reg .u64 t; cvta.to.shared.u64 t, %1; cvt.u32.u64 %0, t; }"
        : "=r"(a) : "l"(p));
    return a;
}
__device__ __forceinline__ void cp16(uint32_t dst, const void* src) {
    asm volatile("cp.async.cg.shared.global [%0], [%1], 16;"
                 :: "r"(dst), "l"(src) : "memory");
}
#define CP_COMMIT() asm volatile("cp.async.commit_group;" ::: "memory")
#define CP_WAIT(n)  asm volatile("cp.async.wait_group %0;" :: "n"(n) : "memory")

__device__ __forceinline__ void ldm_x4(uint32_t* r, uint32_t addr) {
    asm volatile("ldmatrix.sync.aligned.m8n8.x4.shared.b16 {%0,%1,%2,%3}, [%4];"
                 : "=r"(r[0]), "=r"(r[1]), "=r"(r[2]), "=r"(r[3]) : "r"(addr));
}
__device__ __forceinline__ void mma_f16(float* d, const uint32_t* a, const uint32_t* b) {
    asm volatile(
        "mma.sync.aligned.m16n8k16.row.col.f32.f16.f16.f32 "
        "{%0,%1,%2,%3}, {%4,%5,%6,%7}, {%8,%9}, {%0,%1,%2,%3};"
        : "+f"(d[0]), "+f"(d[1]), "+f"(d[2]), "+f"(d[3])
        : "r"(a[0]), "r"(a[1]), "r"(a[2]), "r"(a[3]), "r"(b[0]), "r"(b[1]));
}
__device__ __forceinline__ uint32_t hmul2u(uint32_t a, uint32_t b) {
    __half2 r = __hmul2(*(__half2*)&a, *(__half2*)&b);
    return *(uint32_t*)&r;
}

// ---------------------------------------------------------------------------
__device__ float g_basis[BATCH * SDIM];
__device__ __align__(16) __half g_F[BATCH * IN_DIM];
// B in mma fragment order: [nblk(16)][kstep(256)][half(2)][lane(32)][4 x u32]
__device__ __align__(16) __half g_Wfrag[OUT_DIM * KDIM];

// ---------------------------------------------------------------------------
// Merged prep.
// blocks 0..255: F fp16 + basis.
// blocks 256..1279: W -> fragment layout. Thread writes one uint4 (4 u32):
//   j=0: (n0,   k0/k0+1)  j=1: (n0,   k0+8/+9)
//   j=2: (n0+8, k0/k0+1)  j=3: (n0+8, k0+8/+9)
// ---------------------------------------------------------------------------
__global__ void prep_kernel(const float* __restrict__ inputs,
                            const float* __restrict__ W) {
    const int bid = blockIdx.x;
    const int tid = threadIdx.x;
    if (bid < 256) {
        const int t0 = bid * 256 + tid;
#pragma unroll
        for (int j = 0; j < 8; ++j) {
            int g = t0 + j * 65536;
            int b = g >> 8, p = g & 255;
            const float* row = inputs + (size_t)b * ROWLEN;
            float x0 = __ldg(row + 1 + 2 * p);
            float x1 = __ldg(row + 2 + 2 * p);
            __half2 h = __floats2half2_rn(x0, x1);
            ((uint32_t*)g_F)[g] = *(uint32_t*)&h;
        }
        if (t0 < BATCH) {
            float tt = __ldg(&inputs[(size_t)t0 * ROWLEN]);
            float t2 = tt * tt, t3 = t2 * tt;
            float* dst = &g_basis[t0 * SDIM];
            dst[0] = 1.0f; dst[1] = tt; dst[2] = t2; dst[3] = t3;
            const float kn[4] = {0.2f, 0.4f, 0.6f, 0.8f};
#pragma unroll
            for (int j = 0; j < 4; ++j) {
                float u = fmaxf(tt - kn[j], 0.0f);
                dst[4 + j] = u * u * u;
            }
        }
    } else {
        const int wb   = bid - 256;                    // 0..1023
        const int lane = tid & 31;
        const int h    = (tid >> 5) & 1;
        const int ks   = (wb * 4 + (tid >> 6)) & 255;
        const int nblk = wb >> 6;
        const int n0 = nblk * 32 + h * 16 + (lane >> 2);
        const int k0 = ks * 16 + (lane & 3) * 2;
        const int s  = k0 >> 9;
        const int i  = k0 & 511;
        const float* Wb = W + ((size_t)s << 18);
        uint32_t v[4];
        {
            __half2 a = __floats2half2_rn(__ldg(&Wb[(size_t)i * 512 + n0]),
                                          __ldg(&Wb[(size_t)(i + 1) * 512 + n0]));
            v[0] = *(uint32_t*)&a;
            __half2 b = __floats2half2_rn(__ldg(&Wb[(size_t)(i + 8) * 512 + n0]),
                                          __ldg(&Wb[(size_t)(i + 9) * 512 + n0]));
            v[1] = *(uint32_t*)&b;
            __half2 c = __floats2half2_rn(__ldg(&Wb[(size_t)i * 512 + n0 + 8]),
                                          __ldg(&Wb[(size_t)(i + 1) * 512 + n0 + 8]));
            v[2] = *(uint32_t*)&c;
            __half2 d = __floats2half2_rn(__ldg(&Wb[(size_t)(i + 8) * 512 + n0 + 8]),
                                          __ldg(&Wb[(size_t)(i + 9) * 512 + n0 + 8]));
            v[3] = *(uint32_t*)&d;
        }
        const size_t u = (size_t)wb * 1024 + tid * 4;   // u32 index
        ((uint4*)g_Wfrag)[u >> 2] = *(uint4*)v;
    }
}

// ---------------------------------------------------------------------------
// GEMM: 2 s-groups x 4 warps (32x32 tiles); A via cp.async + per-chunk ldmatrix
// into registers; B via LDG.128 in fragment layout (no smem, no per-iter bar);
// fp16 basis scaling on A fragments; cross-group reduction; 2 CTAs/SM.
// ---------------------------------------------------------------------------
__global__ __launch_bounds__(NTH, 2)
void vclinear_mma_kernel(const float* __restrict__ bwts, float* __restrict__ out) {
    extern __shared__ char smem[];
    const uint32_t sb = smem_u32(smem);
    const int tid  = threadIdx.x;
    const int g    = tid >> 7;
    const int gwid = (tid >> 5) & 3;
    const int lane = tid & 31;
    const int block_n = blockIdx.x * BN;
    const int block_m = blockIdx.y * BM;

    float* sBasis = (float*)(smem + OFF_BASIS);
    float* sBw    = (float*)(smem + OFF_BW);
    for (int q = tid; q < BM * SDIM; q += NTH)
        sBasis[q] = g_basis[(block_m + (q >> 3)) * SDIM + (q & 7)];
    for (int q = tid; q < SDIM * BN; q += NTH)
        sBw[q] = bwts[(q >> 5) * OUT_DIM + block_n + (q & 31)];

    const int ca = tid & 7;
    const int ra = tid >> 3;

#define LOAD_A(chunk) do {                                                       \
    const uint32_t d = sb + OFF_A + ((chunk) & 1) * A_BUF_BYTES;                 \
    const size_t base = (size_t)block_m * IN_DIM + (chunk) * CHUNK + ca * 8;     \
    _Pragma("unroll")                                                            \
    for (int j = 0; j < 4; ++j) {                                                \
        int row = ra + j * 32;                                                   \
        cp16(d + row * SROWB + ca * 16, g_F + base + (size_t)row * IN_DIM);      \
    }                                                                            \
} while (0)

    const int m0 = gwid * 32;
    const uint32_t aoff = (m0 + (lane & 15)) * SROWB + (lane >> 4) * 16;

    // B fragment base for this n-block (uint4 units): 256 ksteps x 64 uint4
    const uint4* Bbase = (const uint4*)g_Wfrag + (size_t)blockIdx.x * 256 * 64 + lane;

#define LDB(dst, kstep) do {                                                     \
    uint4 x = __ldg(Bbase + (kstep) * 64);                                       \
    uint4 y = __ldg(Bbase + (kstep) * 64 + 32);                                  \
    (dst)[0] = x.x; (dst)[1] = x.y; (dst)[2] = x.z; (dst)[3] = x.w;              \
    (dst)[4] = y.x; (dst)[5] = y.y; (dst)[6] = y.z; (dst)[7] = y.w;              \
} while (0)

    uint32_t af[4][2][4];
    float acc[2][4][4];
#pragma unroll
    for (int i = 0; i < 2; ++i)
#pragma unroll
        for (int j = 0; j < 4; ++j)
#pragma unroll
            for (int r = 0; r < 4; ++r) acc[i][j][r] = 0.0f;

    // prologue
    LOAD_A(0);
    CP_COMMIT();
    uint32_t bq[2][8];
    LDB(bq[0], (g * 4) * 32);   // chunk0, it0, kk0
    __syncthreads();            // sBasis/sBw visible

    for (int chunk = 0; chunk < 8; ++chunk) {
        CP_WAIT(0);
        __syncthreads();
        if (chunk < 7) LOAD_A(chunk + 1);
        CP_COMMIT();

        // A tile -> registers for this chunk
        const uint32_t aB = sb + OFF_A + (chunk & 1) * A_BUF_BYTES;
#pragma unroll
        for (int kk = 0; kk < 4; ++kk)
#pragma unroll
            for (int ma = 0; ma < 2; ++ma)
                ldm_x4(af[kk][ma], aB + aoff + ma * 16 * SROWB + kk * 32);

#pragma unroll
        for (int it = 0; it < 4; ++it) {
            const int s = g * 4 + it;
            uint32_t hb[4];
#pragma unroll
            for (int i = 0; i < 4; ++i) {
                float bv = sBasis[(m0 + (lane >> 2) + 8 * i) * SDIM + s];
                __half2 h = __float2half2_rn(bv);
                hb[i] = *(uint32_t*)&h;
            }
#pragma unroll
            for (int kk = 0; kk < 4; ++kk) {
                const int lin = it * 4 + kk;        // 0..15 within chunk
                const int pb  = (chunk * 16 + lin) & 1;
                // prefetch next kstep's B
                if (chunk < 7 || lin < 15) {
                    const int nl   = lin + 1;
                    const int nc   = chunk + (nl >> 4);
                    const int nrem = nl & 15;
                    const int nks  = (g * 4 + (nrem >> 2)) * 32 + nc * 4 + (nrem & 3);
                    LDB(bq[pb ^ 1], nks);
                }
#pragma unroll
                for (int ma = 0; ma < 2; ++ma) {
                    uint32_t at[4];
                    at[0] = hmul2u(af[kk][ma][0], hb[2 * ma]);
                    at[1] = hmul2u(af[kk][ma][1], hb[2 * ma + 1]);
                    at[2] = hmul2u(af[kk][ma][2], hb[2 * ma]);
                    at[3] = hmul2u(af[kk][ma][3], hb[2 * ma + 1]);
#pragma unroll
                    for (int na = 0; na < 4; ++na)
                        mma_f16(acc[ma][na], at, &bq[pb][na * 2]);
                }
            }
        }
    }

    // cross-group reduction: g1 stages partials, g0 adds + bias + store
    float* red = (float*)(smem + OFF_A);
    __syncthreads();
    if (g == 1) {
#pragma unroll
        for (int ma = 0; ma < 2; ++ma)
#pragma unroll
            for (int half = 0; half < 2; ++half) {
                const int row = m0 + ma * 16 + (lane >> 2) + half * 8;
#pragma unroll
                for (int na = 0; na < 4; ++na) {
                    const int col = na * 8 + 2 * (lane & 3);
                    *(float2*)&red[row * RED_STRIDE + col] =
                        make_float2(acc[ma][na][half * 2], acc[ma][na][half * 2 + 1]);
                }
            }
    }
    __syncthreads();
    if (g == 0) {
#pragma unroll
        for (int ma = 0; ma < 2; ++ma) {
#pragma unroll
            for (int half = 0; half < 2; ++half) {
                const int row = m0 + ma * 16 + (lane >> 2) + half * 8;
                float bsv[SDIM];
#pragma unroll
                for (int s = 0; s < SDIM; ++s) bsv[s] = sBasis[row * SDIM + s];
#pragma unroll
                for (int na = 0; na < 4; ++na) {
                    const int col = na * 8 + 2 * (lane & 3);
                    float b0r = 0.0f, b1r = 0.0f;
#pragma unroll
                    for (int s = 0; s < SDIM; ++s) {
                        b0r = fmaf(bsv[s], sBw[s * BN + col], b0r);
                        b1r = fmaf(bsv[s], sBw[s * BN + col + 1], b1r);
                    }
                    float2 o = *(float2*)&red[row * RED_STRIDE + col];
                    float2 v;
                    v.x = acc[ma][na][half * 2 + 0] + o.x + b0r;
                    v.y = acc[ma][na][half * 2 + 1] + o.y + b1r;
                    *(float2*)&out[(size_t)(block_m + row) * OUT_DIM + block_n + col] = v;
                }
            }
        }
    }
}

// ---------------------------------------------------------------------------
extern "C" void kernel_launch(void* const* d_in, const int* in_sizes, int n_in,
                              void* d_out, int out_size) {
    const float* inputs = (const float*)d_in[0];
    const float* W      = (const float*)d_in[1];
    const float* bwts   = (const float*)d_in[2];
    float* out          = (float*)d_out;

    cudaFuncSetAttribute(vclinear_mma_kernel,
                         cudaFuncAttributeMaxDynamicSharedMemorySize, SMEM_TOTAL);

    prep_kernel<<<1280, 256>>>(inputs, W);

    dim3 grid(OUT_DIM / BN, BATCH / BM);   // (16, 16) = 256 CTAs, 2/SM
    vclinear_mma_kernel<<<grid, NTH, SMEM_TOTAL>>>(bwts, out);
}

// round 13
// speedup vs baseline: 1.2391x; 1.0571x over previous
#include <cuda_runtime.h>
#include <cuda_fp16.h>
#include <cstdint>

#define BATCH   2048
#define IN_DIM  512
#define OUT_DIM 512
#define SDIM    8
#define KDIM    4096
#define ROWLEN  513

#define BM 128
#define BN 32
#define NTH 256                      // 2 s-groups x 4 warps

#define OFF_BASIS 0
#define OFF_BW    (BM * SDIM * 4)                  // 4096
#define OFF_RED   (OFF_BW + SDIM * BN * 4)         // 5120
#define RED_STRIDE 34
#define SMEM_TOTAL (OFF_RED + BM * RED_STRIDE * 4) // 22528

// ---------------------------------------------------------------------------
__device__ __forceinline__ uint32_t smem_u32(const void* p) {
    uint32_t a;
    asm("{ .reg .u64 t; cvta.to.shared.u64 t, %1; cvt.u32.u64 %0, t; }"
        : "=r"(a) : "l"(p));
    return a;
}
__device__ __forceinline__ void mma_f16(float* d, const uint32_t* a, const uint32_t* b) {
    asm volatile(
        "mma.sync.aligned.m16n8k16.row.col.f32.f16.f16.f32 "
        "{%0,%1,%2,%3}, {%4,%5,%6,%7}, {%8,%9}, {%0,%1,%2,%3};"
        : "+f"(d[0]), "+f"(d[1]), "+f"(d[2]), "+f"(d[3])
        : "r"(a[0]), "r"(a[1]), "r"(a[2]), "r"(a[3]), "r"(b[0]), "r"(b[1]));
}
__device__ __forceinline__ uint32_t hmul2u(uint32_t a, uint32_t b) {
    __half2 r = __hmul2(*(__half2*)&a, *(__half2*)&b);
    return *(uint32_t*)&r;
}

// ---------------------------------------------------------------------------
__device__ float g_basis[BATCH * SDIM];
// A in mma fragment order: [mblk16][iks32][wm4][h2][lane32][4 u32]  (2 MB)
__device__ __align__(16) __half g_Afrag[BATCH * IN_DIM];
// B in mma fragment order: [nblk16][kstep256][half2][lane32][4 u32] (4 MB)
__device__ __align__(16) __half g_Wfrag[OUT_DIM * KDIM];

// ---------------------------------------------------------------------------
// Prep:
//  blocks 0..511    : A fragments for (mblk=bid>>5, iks=bid&31); ks==0 blocks
//                     also compute basis for their 128 rows.
//  blocks 512..1535 : B fragments (same as R12).
// ---------------------------------------------------------------------------
__global__ void prep_kernel(const float* __restrict__ inputs,
                            const float* __restrict__ W) {
    const int bid = blockIdx.x;
    const int tid = threadIdx.x;
    if (bid < 512) {
        const int mblk = bid >> 5;
        const int iks  = bid & 31;
        const int wm   = tid >> 6;
        const int h    = (tid >> 5) & 1;
        const int lane = tid & 31;
        const int rowbase = mblk * 128 + wm * 32 + h * 16 + (lane >> 2);
        const int i0 = iks * 16 + (lane & 3) * 2;
        const float* rp0 = inputs + (size_t)rowbase * ROWLEN + 1 + i0;
        const float* rp8 = rp0 + 8 * ROWLEN;
        uint32_t v[4];
        {
            __half2 a = __floats2half2_rn(__ldg(rp0),     __ldg(rp0 + 1));
            __half2 b = __floats2half2_rn(__ldg(rp8),     __ldg(rp8 + 1));
            __half2 c = __floats2half2_rn(__ldg(rp0 + 8), __ldg(rp0 + 9));
            __half2 d = __floats2half2_rn(__ldg(rp8 + 8), __ldg(rp8 + 9));
            v[0] = *(uint32_t*)&a; v[1] = *(uint32_t*)&b;
            v[2] = *(uint32_t*)&c; v[3] = *(uint32_t*)&d;
        }
        ((uint4*)g_Afrag)[(size_t)bid * 256 + tid] = *(uint4*)v;

        if (iks == 0 && tid < 128) {
            const int row = mblk * 128 + tid;
            float tt = __ldg(&inputs[(size_t)row * ROWLEN]);
            float t2 = tt * tt, t3 = t2 * tt;
            float* dst = &g_basis[row * SDIM];
            dst[0] = 1.0f; dst[1] = tt; dst[2] = t2; dst[3] = t3;
            const float kn[4] = {0.2f, 0.4f, 0.6f, 0.8f};
#pragma unroll
            for (int j = 0; j < 4; ++j) {
                float u = fmaxf(tt - kn[j], 0.0f);
                dst[4 + j] = u * u * u;
            }
        }
    } else {
        const int wb   = bid - 512;                    // 0..1023
        const int lane = tid & 31;
        const int h    = (tid >> 5) & 1;
        const int ks   = (wb * 4 + (tid >> 6)) & 255;
        const int nblk = wb >> 6;
        const int n0 = nblk * 32 + h * 16 + (lane >> 2);
        const int k0 = ks * 16 + (lane & 3) * 2;
        const int s  = k0 >> 9;
        const int i  = k0 & 511;
        const float* Wb = W + ((size_t)s << 18);
        uint32_t v[4];
        {
            __half2 a = __floats2half2_rn(__ldg(&Wb[(size_t)i * 512 + n0]),
                                          __ldg(&Wb[(size_t)(i + 1) * 512 + n0]));
            __half2 b = __floats2half2_rn(__ldg(&Wb[(size_t)(i + 8) * 512 + n0]),
                                          __ldg(&Wb[(size_t)(i + 9) * 512 + n0]));
            __half2 c = __floats2half2_rn(__ldg(&Wb[(size_t)i * 512 + n0 + 8]),
                                          __ldg(&Wb[(size_t)(i + 1) * 512 + n0 + 8]));
            __half2 d = __floats2half2_rn(__ldg(&Wb[(size_t)(i + 8) * 512 + n0 + 8]),
                                          __ldg(&Wb[(size_t)(i + 9) * 512 + n0 + 8]));
            v[0] = *(uint32_t*)&a; v[1] = *(uint32_t*)&b;
            v[2] = *(uint32_t*)&c; v[3] = *(uint32_t*)&d;
        }
        ((uint4*)g_Wfrag)[(size_t)wb * 256 + tid] = *(uint4*)v;
    }
}

// ---------------------------------------------------------------------------
// GEMM: barrier-free mainloop. Both A and B streamed via LDG.128 in fragment
// layout; fp16 basis scaling on A; 2 s-groups x 4 warps; 2 CTAs/SM.
// ---------------------------------------------------------------------------
__global__ __launch_bounds__(NTH, 2)
void vclinear_mma_kernel(const float* __restrict__ bwts, float* __restrict__ out) {
    extern __shared__ char smem[];
    const int tid  = threadIdx.x;
    const int g    = tid >> 7;              // s-group 0/1
    const int gwid = (tid >> 5) & 3;        // warp m-position
    const int lane = tid & 31;
    const int block_n = blockIdx.x * BN;
    const int block_m = blockIdx.y * BM;

    float* sBasis = (float*)(smem + OFF_BASIS);
    float* sBw    = (float*)(smem + OFF_BW);
    for (int q = tid; q < BM * SDIM; q += NTH)
        sBasis[q] = g_basis[(block_m + (q >> 3)) * SDIM + (q & 7)];
    for (int q = tid; q < SDIM * BN; q += NTH)
        sBw[q] = bwts[(q >> 5) * OUT_DIM + block_n + (q & 31)];
    __syncthreads();

    const int m0 = gwid * 32;

    // A frag base (uint4 units): [mblk][iks]*256 + wm*64 + h*32 + lane
    const uint4* Ab = (const uint4*)g_Afrag
                    + (size_t)blockIdx.y * 8192 + gwid * 64 + lane;
    // B frag base: [nblk]*16384 + kstep*64 + h*32 + lane
    const uint4* Bb = (const uint4*)g_Wfrag
                    + (size_t)blockIdx.x * 16384 + lane;

#define LDA(dst, iks) do {                                                      \
    uint4 x = __ldg(Ab + (iks) * 256);                                          \
    uint4 y = __ldg(Ab + (iks) * 256 + 32);                                     \
    (dst)[0] = x.x; (dst)[1] = x.y; (dst)[2] = x.z; (dst)[3] = x.w;             \
    (dst)[4] = y.x; (dst)[5] = y.y; (dst)[6] = y.z; (dst)[7] = y.w;             \
} while (0)

#define LDB(dst, kstep) do {                                                    \
    uint4 x = __ldg(Bb + (kstep) * 64);                                         \
    uint4 y = __ldg(Bb + (kstep) * 64 + 32);                                    \
    (dst)[0] = x.x; (dst)[1] = x.y; (dst)[2] = x.z; (dst)[3] = x.w;             \
    (dst)[4] = y.x; (dst)[5] = y.y; (dst)[6] = y.z; (dst)[7] = y.w;             \
} while (0)

    float acc[2][4][4];
#pragma unroll
    for (int i = 0; i < 2; ++i)
#pragma unroll
        for (int j = 0; j < 4; ++j)
#pragma unroll
            for (int r = 0; r < 4; ++r) acc[i][j][r] = 0.0f;

    uint32_t aq[2][8], bq[2][8];
    LDA(aq[0], 0);
    LDB(bq[0], g * 128);

    for (int s4 = 0; s4 < 4; ++s4) {
        const int s = g * 4 + s4;
        uint32_t hb[4];
#pragma unroll
        for (int i = 0; i < 4; ++i) {
            float bv = sBasis[(m0 + (lane >> 2) + 8 * i) * SDIM + s];
            __half2 h = __float2half2_rn(bv);
            hb[i] = *(uint32_t*)&h;
        }
#pragma unroll 4
        for (int iks = 0; iks < 32; ++iks) {
            const int lin = s4 * 32 + iks;
            const int pb  = lin & 1;
            if (lin < 127) {
                LDA(aq[pb ^ 1], (lin + 1) & 31);
                LDB(bq[pb ^ 1], g * 128 + lin + 1);
            }
#pragma unroll
            for (int ma = 0; ma < 2; ++ma) {
                uint32_t at[4];
                at[0] = hmul2u(aq[pb][ma * 4 + 0], hb[2 * ma]);
                at[1] = hmul2u(aq[pb][ma * 4 + 1], hb[2 * ma + 1]);
                at[2] = hmul2u(aq[pb][ma * 4 + 2], hb[2 * ma]);
                at[3] = hmul2u(aq[pb][ma * 4 + 3], hb[2 * ma + 1]);
#pragma unroll
                for (int na = 0; na < 4; ++na)
                    mma_f16(acc[ma][na], at, &bq[pb][na * 2]);
            }
        }
    }

    // cross-group reduction: g1 stages partials, g0 adds + bias + store
    float* red = (float*)(smem + OFF_RED);
    __syncthreads();
    if (g == 1) {
#pragma unroll
        for (int ma = 0; ma < 2; ++ma)
#pragma unroll
            for (int half = 0; half < 2; ++half) {
                const int row = m0 + ma * 16 + (lane >> 2) + half * 8;
#pragma unroll
                for (int na = 0; na < 4; ++na) {
                    const int col = na * 8 + 2 * (lane & 3);
                    *(float2*)&red[row * RED_STRIDE + col] =
                        make_float2(acc[ma][na][half * 2], acc[ma][na][half * 2 + 1]);
                }
            }
    }
    __syncthreads();
    if (g == 0) {
#pragma unroll
        for (int ma = 0; ma < 2; ++ma) {
#pragma unroll
            for (int half = 0; half < 2; ++half) {
                const int row = m0 + ma * 16 + (lane >> 2) + half * 8;
                float bsv[SDIM];
#pragma unroll
                for (int s = 0; s < SDIM; ++s) bsv[s] = sBasis[row * SDIM + s];
#pragma unroll
                for (int na = 0; na < 4; ++na) {
                    const int col = na * 8 + 2 * (lane & 3);
                    float b0r = 0.0f, b1r = 0.0f;
#pragma unroll
                    for (int s = 0; s < SDIM; ++s) {
                        b0r = fmaf(bsv[s], sBw[s * BN + col], b0r);
                        b1r = fmaf(bsv[s], sBw[s * BN + col + 1], b1r);
                    }
                    float2 o = *(float2*)&red[row * RED_STRIDE + col];
                    float2 v;
                    v.x = acc[ma][na][half * 2 + 0] + o.x + b0r;
                    v.y = acc[ma][na][half * 2 + 1] + o.y + b1r;
                    *(float2*)&out[(size_t)(block_m + row) * OUT_DIM + block_n + col] = v;
                }
            }
        }
    }
}

// ---------------------------------------------------------------------------
extern "C" void kernel_launch(void* const* d_in, const int* in_sizes, int n_in,
                              void* d_out, int out_size) {
    const float* inputs = (const float*)d_in[0];
    const float* W      = (const float*)d_in[1];
    const float* bwts   = (const float*)d_in[2];
    float* out          = (float*)d_out;

    cudaFuncSetAttribute(vclinear_mma_kernel,
                         cudaFuncAttributeMaxDynamicSharedMemorySize, SMEM_TOTAL);

    prep_kernel<<<1536, 256>>>(inputs, W);

    dim3 grid(OUT_DIM / BN, BATCH / BM);   // (16, 16) = 256 CTAs, 2/SM
    vclinear_mma_kernel<<<grid, NTH, SMEM_TOTAL>>>(bwts, out);
}